// round 1
// baseline (speedup 1.0000x reference)
#include <cuda_runtime.h>
#include <math.h>

#define FIN 512
#define HD  16
#define CD  7
#define NMAX 100000

// Scratch (static device globals — allocation-free rule)
__device__ float g_h1  [NMAX * HD];
__device__ float g_agg1[NMAX * HD];
__device__ float g_h2  [NMAX * 8];   // 7 classes padded to 8 for 16B-aligned vector REDs
__device__ float g_agg2[NMAX * 8];
__device__ float g_dinv[NMAX];

__device__ __forceinline__ void red_add_v4(float* p, float a, float b, float c, float d) {
    asm volatile("red.global.add.v4.f32 [%0], {%1, %2, %3, %4};"
                 :: "l"(p), "f"(a), "f"(b), "f"(c), "f"(d) : "memory");
}

// ---------------- degree / normalization ----------------

__global__ void k_init_deg(int n) {
    int i = blockIdx.x * blockDim.x + threadIdx.x;
    if (i < n) g_dinv[i] = 1.0f;              // self-loop
}

__global__ void k_deg(const int* __restrict__ dst, int e) {
    int i = blockIdx.x * blockDim.x + threadIdx.x;
    if (i < e) atomicAdd(&g_dinv[dst[i]], 1.0f);
}

__global__ void k_rsqrt(int n) {
    int i = blockIdx.x * blockDim.x + threadIdx.x;
    if (i < n) g_dinv[i] = rsqrtf(g_dinv[i]); // deg >= 1 always (self-loop)
}

// ---------------- GEMM1: h1 = x @ W1  (N x 512 @ 512 x 16) ----------------
// Block = 256 threads computes a 256-node x 16-col tile.
// Thread (ng, jg): 4 nodes (ng*4..+3) x 4 cols (jg*4..+3) register micro-tile.
// x tile staged node-major with stride 33 (conflict-free STS and LDS).

__global__ __launch_bounds__(256) void k_gemm1(const float* __restrict__ x,
                                               const float* __restrict__ W1, int n) {
    __shared__ float4 sW[32 * 4];        // 32 k x 16 j
    __shared__ float  sX[256 * 33];      // 256 nodes x 32 k (+1 pad)

    const int t  = threadIdx.x;
    const int n0 = blockIdx.x * 256;
    const int ng = t >> 2;               // 0..63
    const int jg = t & 3;                // 0..3

    float acc[4][4];
#pragma unroll
    for (int a = 0; a < 4; a++)
#pragma unroll
        for (int b = 0; b < 4; b++) acc[a][b] = 0.0f;

    for (int k0 = 0; k0 < FIN; k0 += 32) {
        __syncthreads();
        if (t < 128) {
            // k = t>>2, jq = t&3 : coalesced float4 loads of W1 tile
            sW[t] = *(const float4*)(W1 + (size_t)(k0 + (t >> 2)) * HD + (t & 3) * 4);
        }
#pragma unroll
        for (int i = 0; i < 8; i++) {
            int f    = t + 256 * i;
            int nl   = f >> 3;           // local node 0..255
            int kq   = f & 7;            // float4 index within 32-k row
            int node = n0 + nl;
            float4 v = make_float4(0.f, 0.f, 0.f, 0.f);
            if (node < n) v = *(const float4*)(x + (size_t)node * FIN + k0 + kq * 4);
            float* sp = &sX[nl * 33 + kq * 4];
            sp[0] = v.x; sp[1] = v.y; sp[2] = v.z; sp[3] = v.w;
        }
        __syncthreads();
#pragma unroll
        for (int k = 0; k < 32; k++) {
            float4 wv = sW[k * 4 + jg];
            float x0 = sX[(ng * 4 + 0) * 33 + k];
            float x1 = sX[(ng * 4 + 1) * 33 + k];
            float x2 = sX[(ng * 4 + 2) * 33 + k];
            float x3 = sX[(ng * 4 + 3) * 33 + k];
            acc[0][0] += x0 * wv.x; acc[0][1] += x0 * wv.y; acc[0][2] += x0 * wv.z; acc[0][3] += x0 * wv.w;
            acc[1][0] += x1 * wv.x; acc[1][1] += x1 * wv.y; acc[1][2] += x1 * wv.z; acc[1][3] += x1 * wv.w;
            acc[2][0] += x2 * wv.x; acc[2][1] += x2 * wv.y; acc[2][2] += x2 * wv.z; acc[2][3] += x2 * wv.w;
            acc[3][0] += x3 * wv.x; acc[3][1] += x3 * wv.y; acc[3][2] += x3 * wv.z; acc[3][3] += x3 * wv.w;
        }
    }
#pragma unroll
    for (int ni = 0; ni < 4; ni++) {
        int node = n0 + ng * 4 + ni;
        if (node < n)
            *(float4*)&g_h1[(size_t)node * HD + jg * 4] =
                make_float4(acc[ni][0], acc[ni][1], acc[ni][2], acc[ni][3]);
    }
}

// ---------------- aggregation layer 1 ----------------

__global__ void k_self1(int n) {      // self-loop message: agg1 = h1 * dinv^2
    int i = blockIdx.x * blockDim.x + threadIdx.x;
    if (i < n * HD) {
        float d = g_dinv[i >> 4];
        g_agg1[i] = g_h1[i] * d * d;
    }
}

__global__ void k_scat1(const int* __restrict__ src, const int* __restrict__ dst, int e) {
    int i = blockIdx.x * blockDim.x + threadIdx.x;
    if (i >= e) return;
    int s = src[i], d = dst[i];
    float nrm = g_dinv[s] * g_dinv[d];
    const float4* hp = (const float4*)(g_h1 + (size_t)s * HD);
    float* op = g_agg1 + (size_t)d * HD;
#pragma unroll
    for (int q = 0; q < 4; q++) {
        float4 v = hp[q];
        red_add_v4(op + q * 4, v.x * nrm, v.y * nrm, v.z * nrm, v.w * nrm);
    }
}

// ---------------- layer 2 transform: h2 = relu(agg1 + b1) @ W2 ----------------

__global__ __launch_bounds__(256) void k_l2(const float* __restrict__ b1,
                                            const float* __restrict__ W2, int n) {
    __shared__ float sW2[HD * CD];
    __shared__ float sb1[HD];
    int t = threadIdx.x;
    if (t < HD * CD) sW2[t] = W2[t];
    if (t < HD)      sb1[t] = b1[t];
    __syncthreads();
    int i = blockIdx.x * blockDim.x + t;
    if (i >= n) return;

    const float4* ap = (const float4*)(g_agg1 + (size_t)i * HD);
    float v[HD];
#pragma unroll
    for (int q = 0; q < 4; q++) {
        float4 a = ap[q];
        v[q * 4 + 0] = fmaxf(a.x + sb1[q * 4 + 0], 0.f);
        v[q * 4 + 1] = fmaxf(a.y + sb1[q * 4 + 1], 0.f);
        v[q * 4 + 2] = fmaxf(a.z + sb1[q * 4 + 2], 0.f);
        v[q * 4 + 3] = fmaxf(a.w + sb1[q * 4 + 3], 0.f);
    }
    float o[8];
#pragma unroll
    for (int c = 0; c < CD; c++) {
        float acc = 0.f;
#pragma unroll
        for (int j = 0; j < HD; j++) acc += v[j] * sW2[j * CD + c];
        o[c] = acc;
    }
    o[7] = 0.f;
    float4* hp = (float4*)(g_h2 + (size_t)i * 8);
    hp[0] = make_float4(o[0], o[1], o[2], o[3]);
    hp[1] = make_float4(o[4], o[5], o[6], o[7]);
}

// ---------------- aggregation layer 2 ----------------

__global__ void k_self2(int n) {
    int i = blockIdx.x * blockDim.x + threadIdx.x;
    if (i < n * 8) {
        float d = g_dinv[i >> 3];
        g_agg2[i] = g_h2[i] * d * d;
    }
}

__global__ void k_scat2(const int* __restrict__ src, const int* __restrict__ dst, int e) {
    int i = blockIdx.x * blockDim.x + threadIdx.x;
    if (i >= e) return;
    int s = src[i], d = dst[i];
    float nrm = g_dinv[s] * g_dinv[d];
    const float4* hp = (const float4*)(g_h2 + (size_t)s * 8);
    float* op = g_agg2 + (size_t)d * 8;
#pragma unroll
    for (int q = 0; q < 2; q++) {
        float4 v = hp[q];
        red_add_v4(op + q * 4, v.x * nrm, v.y * nrm, v.z * nrm, v.w * nrm);
    }
}

// ---------------- bias + log_softmax ----------------

__global__ __launch_bounds__(256) void k_out(const float* __restrict__ b2,
                                             float* __restrict__ out, int n) {
    __shared__ float sb2[CD];
    int t = threadIdx.x;
    if (t < CD) sb2[t] = b2[t];
    __syncthreads();
    int i = blockIdx.x * blockDim.x + t;
    if (i >= n) return;

    const float4* ap = (const float4*)(g_agg2 + (size_t)i * 8);
    float4 a = ap[0], b = ap[1];
    float o[CD] = { a.x + sb2[0], a.y + sb2[1], a.z + sb2[2], a.w + sb2[3],
                    b.x + sb2[4], b.y + sb2[5], b.z + sb2[6] };
    float m = o[0];
#pragma unroll
    for (int c = 1; c < CD; c++) m = fmaxf(m, o[c]);
    float s = 0.f;
#pragma unroll
    for (int c = 0; c < CD; c++) s += expf(o[c] - m);
    float l = m + logf(s);
#pragma unroll
    for (int c = 0; c < CD; c++) out[(size_t)i * CD + c] = o[c] - l;
}

// ---------------- launch ----------------

extern "C" void kernel_launch(void* const* d_in, const int* in_sizes, int n_in,
                              void* d_out, int out_size) {
    const float* x  = (const float*)d_in[0];
    const int*   ei = (const int*)  d_in[1];
    const float* W1 = (const float*)d_in[2];
    const float* b1 = (const float*)d_in[3];
    const float* W2 = (const float*)d_in[4];
    const float* b2 = (const float*)d_in[5];

    const int n = in_sizes[0] / FIN;
    const int e = in_sizes[1] / 2;
    const int* src = ei;
    const int* dst = ei + e;

    const int TB = 256;
    k_init_deg<<<(n + TB - 1) / TB, TB>>>(n);
    k_deg     <<<(e + TB - 1) / TB, TB>>>(dst, e);
    k_rsqrt   <<<(n + TB - 1) / TB, TB>>>(n);

    k_gemm1   <<<(n + 255) / 256, 256>>>(x, W1, n);
    k_self1   <<<(n * HD + TB - 1) / TB, TB>>>(n);
    k_scat1   <<<(e + TB - 1) / TB, TB>>>(src, dst, e);

    k_l2      <<<(n + TB - 1) / TB, TB>>>(b1, W2, n);
    k_self2   <<<(n * 8 + TB - 1) / TB, TB>>>(n);
    k_scat2   <<<(e + TB - 1) / TB, TB>>>(src, dst, e);

    k_out     <<<(n + TB - 1) / TB, TB>>>(b2, (float*)d_out, n);
}

// round 2
// speedup vs baseline: 1.2374x; 1.2374x over previous
#include <cuda_runtime.h>
#include <math.h>

#define FIN 512
#define HD  16
#define CD  7
#define NMAX 100000
#define EMAX 3200000

// ---------------- scratch (static device globals) ----------------
__device__ int   g_cnt [NMAX];        // in-degree (without self-loop)
__device__ int   g_rows[NMAX];        // CSR row start
__device__ int   g_cur [NMAX];        // fill cursor
__device__ int   g_bsum[128];         // scan block sums
__device__ float g_dinv[NMAX];
__device__ int   g_csrc[EMAX];        // CSR: source node per edge slot
__device__ float g_cnrm[EMAX];        // CSR: precomputed dinv[s]*dinv[d]
__device__ float g_h1  [NMAX * HD];
__device__ float g_agg1[NMAX * HD];
__device__ float g_h2  [NMAX * 8];    // 7 classes padded to 8
__device__ float g_agg2[NMAX * 8];

// ---------------- degree / CSR build ----------------

__global__ void k_zero(int n) {
    int i = blockIdx.x * blockDim.x + threadIdx.x;
    if (i < n) g_cnt[i] = 0;
}

__global__ void k_cnt(const int* __restrict__ dst, int e) {
    int i = blockIdx.x * blockDim.x + threadIdx.x;
    if (i < e) atomicAdd(&g_cnt[dst[i]], 1);
}

__global__ void k_rsqrt(int n) {
    int i = blockIdx.x * blockDim.x + threadIdx.x;
    if (i < n) g_dinv[i] = rsqrtf((float)(g_cnt[i] + 1));  // +1 self-loop
}

// exclusive scan of g_cnt -> g_rows.  1024 elems / block of 256 threads.
__global__ __launch_bounds__(256) void k_scan1(int n) {
    __shared__ int s[256];
    int t = threadIdx.x;
    int base = blockIdx.x * 1024 + t * 4;
    int v0 = (base + 0 < n) ? g_cnt[base + 0] : 0;
    int v1 = (base + 1 < n) ? g_cnt[base + 1] : 0;
    int v2 = (base + 2 < n) ? g_cnt[base + 2] : 0;
    int v3 = (base + 3 < n) ? g_cnt[base + 3] : 0;
    int ts = v0 + v1 + v2 + v3;
    s[t] = ts;
    __syncthreads();
#pragma unroll
    for (int off = 1; off < 256; off <<= 1) {
        int x = (t >= off) ? s[t - off] : 0;
        __syncthreads();
        s[t] += x;
        __syncthreads();
    }
    int excl = s[t] - ts;
    if (t == 255) g_bsum[blockIdx.x] = s[255];
    int r = excl;
    if (base + 0 < n) { g_rows[base + 0] = r; r += v0; }
    if (base + 1 < n) { g_rows[base + 1] = r; r += v1; }
    if (base + 2 < n) { g_rows[base + 2] = r; r += v2; }
    if (base + 3 < n) { g_rows[base + 3] = r; }
}

__global__ void k_scan2(int nb) {   // one block; nb <= 128
    __shared__ int s[128];
    int t = threadIdx.x;
    if (t < nb) s[t] = g_bsum[t];
    __syncthreads();
    if (t == 0) {
        int acc = 0;
        for (int i = 0; i < nb; i++) { int v = s[i]; s[i] = acc; acc += v; }
    }
    __syncthreads();
    if (t < nb) g_bsum[t] = s[t];
}

__global__ void k_scan3(int n) {
    int i = blockIdx.x * blockDim.x + threadIdx.x;
    if (i < n) {
        int r = g_rows[i] + g_bsum[i >> 10];
        g_rows[i] = r;
        g_cur[i]  = r;
    }
}

__global__ void k_fill(const int* __restrict__ src, const int* __restrict__ dst, int e) {
    int i = blockIdx.x * blockDim.x + threadIdx.x;
    if (i >= e) return;
    int s = src[i], d = dst[i];
    int pos = atomicAdd(&g_cur[d], 1);
    g_csrc[pos] = s;
    g_cnrm[pos] = g_dinv[s] * g_dinv[d];
}

// ---------------- GEMM1: h1 = x @ W1  (N x 512 @ 512 x 16) ----------------

__global__ __launch_bounds__(256) void k_gemm1(const float* __restrict__ x,
                                               const float* __restrict__ W1, int n) {
    __shared__ float4 sW[32 * 4];        // 32 k x 16 j
    __shared__ float  sX[256 * 33];      // 256 nodes x 32 k (+1 pad)

    const int t  = threadIdx.x;
    const int n0 = blockIdx.x * 256;
    const int ng = t >> 2;
    const int jg = t & 3;

    float acc[4][4];
#pragma unroll
    for (int a = 0; a < 4; a++)
#pragma unroll
        for (int b = 0; b < 4; b++) acc[a][b] = 0.0f;

    for (int k0 = 0; k0 < FIN; k0 += 32) {
        __syncthreads();
        if (t < 128)
            sW[t] = *(const float4*)(W1 + (size_t)(k0 + (t >> 2)) * HD + (t & 3) * 4);
#pragma unroll
        for (int i = 0; i < 8; i++) {
            int f    = t + 256 * i;
            int nl   = f >> 3;
            int kq   = f & 7;
            int node = n0 + nl;
            float4 v = make_float4(0.f, 0.f, 0.f, 0.f);
            if (node < n) v = *(const float4*)(x + (size_t)node * FIN + k0 + kq * 4);
            float* sp = &sX[nl * 33 + kq * 4];
            sp[0] = v.x; sp[1] = v.y; sp[2] = v.z; sp[3] = v.w;
        }
        __syncthreads();
#pragma unroll
        for (int k = 0; k < 32; k++) {
            float4 wv = sW[k * 4 + jg];
            float x0 = sX[(ng * 4 + 0) * 33 + k];
            float x1 = sX[(ng * 4 + 1) * 33 + k];
            float x2 = sX[(ng * 4 + 2) * 33 + k];
            float x3 = sX[(ng * 4 + 3) * 33 + k];
            acc[0][0] += x0 * wv.x; acc[0][1] += x0 * wv.y; acc[0][2] += x0 * wv.z; acc[0][3] += x0 * wv.w;
            acc[1][0] += x1 * wv.x; acc[1][1] += x1 * wv.y; acc[1][2] += x1 * wv.z; acc[1][3] += x1 * wv.w;
            acc[2][0] += x2 * wv.x; acc[2][1] += x2 * wv.y; acc[2][2] += x2 * wv.z; acc[2][3] += x2 * wv.w;
            acc[3][0] += x3 * wv.x; acc[3][1] += x3 * wv.y; acc[3][2] += x3 * wv.z; acc[3][3] += x3 * wv.w;
        }
    }
#pragma unroll
    for (int ni = 0; ni < 4; ni++) {
        int node = n0 + ng * 4 + ni;
        if (node < n)
            *(float4*)&g_h1[(size_t)node * HD + jg * 4] =
                make_float4(acc[ni][0], acc[ni][1], acc[ni][2], acc[ni][3]);
    }
}

// ---------------- aggregation layer 1: gather over CSR ----------------
// 4 lanes per node; lane c owns features [4c, 4c+4). Self-loop fused as init.

__global__ __launch_bounds__(256) void k_agg1(int n) {
    int t = threadIdx.x;
    int node = blockIdx.x * 64 + (t >> 2);
    int c = t & 3;
    if (node >= n) return;

    float dv = g_dinv[node];
    float4 acc = *(const float4*)(g_h1 + (size_t)node * HD + c * 4);
    float dv2 = dv * dv;
    acc.x *= dv2; acc.y *= dv2; acc.z *= dv2; acc.w *= dv2;

    int st  = g_rows[node];
    int cnt = g_cnt[node];
    int j = 0;
    for (; j + 1 < cnt; j += 2) {
        int   s0 = g_csrc[st + j],     s1 = g_csrc[st + j + 1];
        float m0 = g_cnrm[st + j],     m1 = g_cnrm[st + j + 1];
        float4 v0 = *(const float4*)(g_h1 + (size_t)s0 * HD + c * 4);
        float4 v1 = *(const float4*)(g_h1 + (size_t)s1 * HD + c * 4);
        acc.x += v0.x * m0 + v1.x * m1;
        acc.y += v0.y * m0 + v1.y * m1;
        acc.z += v0.z * m0 + v1.z * m1;
        acc.w += v0.w * m0 + v1.w * m1;
    }
    if (j < cnt) {
        int   s0 = g_csrc[st + j];
        float m0 = g_cnrm[st + j];
        float4 v0 = *(const float4*)(g_h1 + (size_t)s0 * HD + c * 4);
        acc.x += v0.x * m0; acc.y += v0.y * m0; acc.z += v0.z * m0; acc.w += v0.w * m0;
    }
    *(float4*)(g_agg1 + (size_t)node * HD + c * 4) = acc;
}

// ---------------- layer 2 transform: h2 = relu(agg1 + b1) @ W2 ----------------

__global__ __launch_bounds__(256) void k_l2(const float* __restrict__ b1,
                                            const float* __restrict__ W2, int n) {
    __shared__ float sW2[HD * CD];
    __shared__ float sb1[HD];
    int t = threadIdx.x;
    if (t < HD * CD) sW2[t] = W2[t];
    if (t < HD)      sb1[t] = b1[t];
    __syncthreads();
    int i = blockIdx.x * blockDim.x + t;
    if (i >= n) return;

    const float4* ap = (const float4*)(g_agg1 + (size_t)i * HD);
    float v[HD];
#pragma unroll
    for (int q = 0; q < 4; q++) {
        float4 a = ap[q];
        v[q * 4 + 0] = fmaxf(a.x + sb1[q * 4 + 0], 0.f);
        v[q * 4 + 1] = fmaxf(a.y + sb1[q * 4 + 1], 0.f);
        v[q * 4 + 2] = fmaxf(a.z + sb1[q * 4 + 2], 0.f);
        v[q * 4 + 3] = fmaxf(a.w + sb1[q * 4 + 3], 0.f);
    }
    float o[8];
#pragma unroll
    for (int c = 0; c < CD; c++) {
        float acc = 0.f;
#pragma unroll
        for (int j = 0; j < HD; j++) acc += v[j] * sW2[j * CD + c];
        o[c] = acc;
    }
    o[7] = 0.f;
    float4* hp = (float4*)(g_h2 + (size_t)i * 8);
    hp[0] = make_float4(o[0], o[1], o[2], o[3]);
    hp[1] = make_float4(o[4], o[5], o[6], o[7]);
}

// ---------------- aggregation layer 2 ----------------
// 2 lanes per node; lane c owns features [4c, 4c+4) of the 8-wide row.

__global__ __launch_bounds__(256) void k_agg2(int n) {
    int t = threadIdx.x;
    int node = blockIdx.x * 128 + (t >> 1);
    int c = t & 1;
    if (node >= n) return;

    float dv = g_dinv[node];
    float4 acc = *(const float4*)(g_h2 + (size_t)node * 8 + c * 4);
    float dv2 = dv * dv;
    acc.x *= dv2; acc.y *= dv2; acc.z *= dv2; acc.w *= dv2;

    int st  = g_rows[node];
    int cnt = g_cnt[node];
    int j = 0;
    for (; j + 1 < cnt; j += 2) {
        int   s0 = g_csrc[st + j],     s1 = g_csrc[st + j + 1];
        float m0 = g_cnrm[st + j],     m1 = g_cnrm[st + j + 1];
        float4 v0 = *(const float4*)(g_h2 + (size_t)s0 * 8 + c * 4);
        float4 v1 = *(const float4*)(g_h2 + (size_t)s1 * 8 + c * 4);
        acc.x += v0.x * m0 + v1.x * m1;
        acc.y += v0.y * m0 + v1.y * m1;
        acc.z += v0.z * m0 + v1.z * m1;
        acc.w += v0.w * m0 + v1.w * m1;
    }
    if (j < cnt) {
        int   s0 = g_csrc[st + j];
        float m0 = g_cnrm[st + j];
        float4 v0 = *(const float4*)(g_h2 + (size_t)s0 * 8 + c * 4);
        acc.x += v0.x * m0; acc.y += v0.y * m0; acc.z += v0.z * m0; acc.w += v0.w * m0;
    }
    *(float4*)(g_agg2 + (size_t)node * 8 + c * 4) = acc;
}

// ---------------- bias + log_softmax ----------------

__global__ __launch_bounds__(256) void k_out(const float* __restrict__ b2,
                                             float* __restrict__ out, int n) {
    __shared__ float sb2[CD];
    int t = threadIdx.x;
    if (t < CD) sb2[t] = b2[t];
    __syncthreads();
    int i = blockIdx.x * blockDim.x + t;
    if (i >= n) return;

    const float4* ap = (const float4*)(g_agg2 + (size_t)i * 8);
    float4 a = ap[0], b = ap[1];
    float o[CD] = { a.x + sb2[0], a.y + sb2[1], a.z + sb2[2], a.w + sb2[3],
                    b.x + sb2[4], b.y + sb2[5], b.z + sb2[6] };
    float m = o[0];
#pragma unroll
    for (int c = 1; c < CD; c++) m = fmaxf(m, o[c]);
    float s = 0.f;
#pragma unroll
    for (int c = 0; c < CD; c++) s += expf(o[c] - m);
    float l = m + logf(s);
#pragma unroll
    for (int c = 0; c < CD; c++) out[(size_t)i * CD + c] = o[c] - l;
}

// ---------------- launch ----------------

extern "C" void kernel_launch(void* const* d_in, const int* in_sizes, int n_in,
                              void* d_out, int out_size) {
    const float* x  = (const float*)d_in[0];
    const int*   ei = (const int*)  d_in[1];
    const float* W1 = (const float*)d_in[2];
    const float* b1 = (const float*)d_in[3];
    const float* W2 = (const float*)d_in[4];
    const float* b2 = (const float*)d_in[5];

    const int n = in_sizes[0] / FIN;
    const int e = in_sizes[1] / 2;
    const int* src = ei;
    const int* dst = ei + e;

    const int TB = 256;
    const int nb_scan = (n + 1023) / 1024;

    // CSR build (shared by both layers)
    k_zero  <<<(n + TB - 1) / TB, TB>>>(n);
    k_cnt   <<<(e + TB - 1) / TB, TB>>>(dst, e);
    k_rsqrt <<<(n + TB - 1) / TB, TB>>>(n);
    k_scan1 <<<nb_scan, 256>>>(n);
    k_scan2 <<<1, 128>>>(nb_scan);
    k_scan3 <<<(n + TB - 1) / TB, TB>>>(n);
    k_fill  <<<(e + TB - 1) / TB, TB>>>(src, dst, e);

    // layer 1
    k_gemm1 <<<(n + 255) / 256, 256>>>(x, W1, n);
    k_agg1  <<<(n + 63) / 64, 256>>>(n);

    // layer 2
    k_l2    <<<(n + TB - 1) / TB, TB>>>(b1, W2, n);
    k_agg2  <<<(n + 127) / 128, 256>>>(n);

    // output
    k_out   <<<(n + TB - 1) / TB, TB>>>(b2, (float*)d_out, n);
}

// round 3
// speedup vs baseline: 1.3729x; 1.1095x over previous
#include <cuda_runtime.h>
#include <math.h>

#define FIN 512
#define HD  16
#define CD  7
#define NMAX 100000
#define EMAX 3200000

typedef unsigned long long u64;

// ---------------- scratch (static device globals) ----------------
__device__ int   g_cnt [NMAX];        // in-degree (without self-loop)
__device__ int   g_rows[NMAX];        // CSR row start
__device__ int   g_cur [NMAX];        // fill cursor
__device__ int   g_bsum[128];         // scan block sums
__device__ float g_dinv[NMAX];
__device__ int2  g_edge[EMAX];        // {src, bitcast(dinv[src])}
__device__ float g_h1  [NMAX * HD];
__device__ float g_h2  [NMAX * 8];    // 7 classes padded to 8 (col7 == 0)

// ---------------- f32x2 helpers ----------------
__device__ __forceinline__ u64 pk2(float lo, float hi) {
    u64 r; asm("mov.b64 %0, {%1, %2};" : "=l"(r) : "f"(lo), "f"(hi)); return r;
}
__device__ __forceinline__ void upk2(float& lo, float& hi, u64 v) {
    asm("mov.b64 {%0, %1}, %2;" : "=f"(lo), "=f"(hi) : "l"(v));
}
__device__ __forceinline__ void fma2(u64& d, u64 a, u64 b) {
    asm("fma.rn.f32x2 %0, %1, %2, %0;" : "+l"(d) : "l"(a), "l"(b));
}

// ---------------- GEMM1 block: h1[tile] = x[tile] @ W1 ----------------
// 256 threads -> 256 nodes x 16 cols. Thread (ng=t>>2, jg=t&3) owns nodes
// ng*4..+3 x cols jg*4..+3, accumulated as f32x2 node-pairs.
// x tile staged global->regs->smem (k-major, stride 258) with double buffering.
__device__ __forceinline__ void gemm1_block(const float* __restrict__ x,
                                            const float* __restrict__ W1,
                                            int n, int bid) {
    __shared__ float4 sW4[128];          // 32 k x 16 j
    __shared__ float  sXT[32 * 258];     // k-major: [k][node], stride 258

    const int t  = threadIdx.x;
    const int n0 = bid * 256;
    const int ng = t >> 2;
    const int jg = t & 3;

    u64 acc[2][4];
#pragma unroll
    for (int p = 0; p < 2; p++)
#pragma unroll
        for (int c = 0; c < 4; c++) acc[p][c] = 0ull;

    float4 rx[8];
    float4 rw = make_float4(0.f, 0.f, 0.f, 0.f);

    // prologue: stage tile k0=0
    if (t < 128) rw = *(const float4*)(W1 + (size_t)(t >> 2) * HD + (t & 3) * 4);
#pragma unroll
    for (int i = 0; i < 8; i++) {
        int f = t + 256 * i;
        int node = n0 + (f >> 3);
        int kq = f & 7;
        rx[i] = (node < n) ? *(const float4*)(x + (size_t)node * FIN + kq * 4)
                           : make_float4(0.f, 0.f, 0.f, 0.f);
    }

#pragma unroll 1
    for (int k0 = 0; k0 < FIN; k0 += 32) {
        if (t < 128) sW4[t] = rw;
#pragma unroll
        for (int i = 0; i < 8; i++) {
            int f = t + 256 * i;
            int nl = f >> 3;
            int kq = f & 7;
            float* sp = &sXT[(kq * 4) * 258 + nl];
            sp[0]   = rx[i].x;
            sp[258] = rx[i].y;
            sp[516] = rx[i].z;
            sp[774] = rx[i].w;
        }
        __syncthreads();
        bool more = (k0 + 32 < FIN);
        if (more) {   // prefetch next tile while computing (LDGs in flight)
            if (t < 128)
                rw = *(const float4*)(W1 + (size_t)(k0 + 32 + (t >> 2)) * HD + (t & 3) * 4);
#pragma unroll
            for (int i = 0; i < 8; i++) {
                int f = t + 256 * i;
                int node = n0 + (f >> 3);
                int kq = f & 7;
                rx[i] = (node < n)
                      ? *(const float4*)(x + (size_t)node * FIN + k0 + 32 + kq * 4)
                      : make_float4(0.f, 0.f, 0.f, 0.f);
            }
        }
#pragma unroll
        for (int k = 0; k < 32; k++) {
            u64 x01 = *(const u64*)&sXT[k * 258 + ng * 4];
            u64 x23 = *(const u64*)&sXT[k * 258 + ng * 4 + 2];
            float4 wv = sW4[k * 4 + jg];
            u64 w0 = pk2(wv.x, wv.x);
            u64 w1 = pk2(wv.y, wv.y);
            u64 w2 = pk2(wv.z, wv.z);
            u64 w3 = pk2(wv.w, wv.w);
            fma2(acc[0][0], x01, w0); fma2(acc[1][0], x23, w0);
            fma2(acc[0][1], x01, w1); fma2(acc[1][1], x23, w1);
            fma2(acc[0][2], x01, w2); fma2(acc[1][2], x23, w2);
            fma2(acc[0][3], x01, w3); fma2(acc[1][3], x23, w3);
        }
        if (more) __syncthreads();
    }

#pragma unroll
    for (int p = 0; p < 2; p++) {
        float lo[4], hi[4];
#pragma unroll
        for (int c = 0; c < 4; c++) upk2(lo[c], hi[c], acc[p][c]);
        int node0 = n0 + ng * 4 + p * 2;
        if (node0 < n)
            *(float4*)&g_h1[(size_t)node0 * HD + jg * 4] =
                make_float4(lo[0], lo[1], lo[2], lo[3]);
        if (node0 + 1 < n)
            *(float4*)&g_h1[(size_t)(node0 + 1) * HD + jg * 4] =
                make_float4(hi[0], hi[1], hi[2], hi[3]);
    }
}

// ---------------- fused launches: CSR work overlapped with GEMM ----------------

__global__ void k_zero(int n) {
    int i = blockIdx.x * blockDim.x + threadIdx.x;
    if (i < n) g_cnt[i] = 0;
}

// launch A: [0,gemmBlocks) run GEMM part A; rest count in-degrees (grid-stride)
__global__ __launch_bounds__(256, 2) void kA(const int* __restrict__ dst, int e,
                                             const float* __restrict__ x,
                                             const float* __restrict__ W1, int n,
                                             int gemmBlocks) {
    if ((int)blockIdx.x < gemmBlocks) { gemm1_block(x, W1, n, blockIdx.x); return; }
    int nb = gridDim.x - gemmBlocks;
    int b  = blockIdx.x - gemmBlocks;
    for (int i = b * 256 + threadIdx.x; i < e; i += nb * 256)
        atomicAdd(&g_cnt[dst[i]], 1);
}

// launch B: [0,gemmBlocks) run GEMM part B; rest fill CSR (grid-stride)
__global__ __launch_bounds__(256, 2) void kB(const int* __restrict__ src,
                                             const int* __restrict__ dst, int e,
                                             const float* __restrict__ x,
                                             const float* __restrict__ W1, int n,
                                             int gemmBlocks, int gemmOffset) {
    if ((int)blockIdx.x < gemmBlocks) {
        gemm1_block(x, W1, n, gemmOffset + blockIdx.x);
        return;
    }
    int nb = gridDim.x - gemmBlocks;
    int b  = blockIdx.x - gemmBlocks;
    for (int i = b * 256 + threadIdx.x; i < e; i += nb * 256) {
        int s = src[i], d = dst[i];
        int pos = atomicAdd(&g_cur[d], 1);
        g_edge[pos] = make_int2(s, __float_as_int(g_dinv[s]));
    }
}

// ---------------- scan (fused with rsqrt of degree) ----------------

__global__ __launch_bounds__(256) void k_scan1_rsqrt(int n, int nbScan) {
    __shared__ int s[256];
    int t = threadIdx.x;
    if ((int)blockIdx.x >= nbScan) {
        int i = ((int)blockIdx.x - nbScan) * 256 + t;
        if (i < n) g_dinv[i] = rsqrtf((float)(g_cnt[i] + 1));   // +1 self-loop
        return;
    }
    int base = blockIdx.x * 1024 + t * 4;
    int v0 = (base + 0 < n) ? g_cnt[base + 0] : 0;
    int v1 = (base + 1 < n) ? g_cnt[base + 1] : 0;
    int v2 = (base + 2 < n) ? g_cnt[base + 2] : 0;
    int v3 = (base + 3 < n) ? g_cnt[base + 3] : 0;
    int ts = v0 + v1 + v2 + v3;
    s[t] = ts;
    __syncthreads();
#pragma unroll
    for (int off = 1; off < 256; off <<= 1) {
        int xv = (t >= off) ? s[t - off] : 0;
        __syncthreads();
        s[t] += xv;
        __syncthreads();
    }
    int excl = s[t] - ts;
    if (t == 255) g_bsum[blockIdx.x] = s[255];
    int r = excl;
    if (base + 0 < n) { g_rows[base + 0] = r; r += v0; }
    if (base + 1 < n) { g_rows[base + 1] = r; r += v1; }
    if (base + 2 < n) { g_rows[base + 2] = r; r += v2; }
    if (base + 3 < n) { g_rows[base + 3] = r; }
}

__global__ void k_scan2(int nb) {   // one block; nb <= 128
    __shared__ int s[128];
    int t = threadIdx.x;
    if (t < nb) s[t] = g_bsum[t];
    __syncthreads();
    if (t == 0) {
        int acc = 0;
        for (int i = 0; i < nb; i++) { int v = s[i]; s[i] = acc; acc += v; }
    }
    __syncthreads();
    if (t < nb) g_bsum[t] = s[t];
}

__global__ void k_scan3(int n) {
    int i = blockIdx.x * blockDim.x + threadIdx.x;
    if (i < n) {
        int r = g_rows[i] + g_bsum[i >> 10];
        g_rows[i] = r;
        g_cur[i]  = r;
    }
}

// ---------------- agg layer 1 + fused layer-2 transform ----------------
// 4 lanes per node; lane c owns feats [4c,4c+4). acc = dv*h1[d] + sum dinv[s]*h1[s];
// result = dv*acc. Then relu(+b1), multiply by W2, 4-lane shuffle reduce -> h2.
__global__ __launch_bounds__(256) void k_agg1(const float* __restrict__ b1,
                                              const float* __restrict__ W2, int n) {
    __shared__ float sW2[HD * 8];
    __shared__ float sb1[HD];
    int t = threadIdx.x;
    if (t < HD * 8) {
        int j = t >> 3, cc = t & 7;
        sW2[t] = (cc < CD) ? W2[j * CD + cc] : 0.f;
    } else if (t < HD * 8 + HD) {
        sb1[t - HD * 8] = b1[t - HD * 8];
    }
    __syncthreads();

    int node = blockIdx.x * 64 + (t >> 2);
    int c = t & 3;
    bool valid = node < n;
    if (!valid) node = n - 1;

    float dv = g_dinv[node];
    float4 h = *(const float4*)(g_h1 + (size_t)node * HD + c * 4);
    float4 acc = make_float4(h.x * dv, h.y * dv, h.z * dv, h.w * dv);

    int st = g_rows[node], cnt = g_cnt[node];
    int j = 0;
    for (; j + 1 < cnt; j += 2) {
        int2 e0 = g_edge[st + j], e1 = g_edge[st + j + 1];
        float m0 = __int_as_float(e0.y), m1 = __int_as_float(e1.y);
        float4 v0 = *(const float4*)(g_h1 + (size_t)e0.x * HD + c * 4);
        float4 v1 = *(const float4*)(g_h1 + (size_t)e1.x * HD + c * 4);
        acc.x += v0.x * m0 + v1.x * m1;
        acc.y += v0.y * m0 + v1.y * m1;
        acc.z += v0.z * m0 + v1.z * m1;
        acc.w += v0.w * m0 + v1.w * m1;
    }
    if (j < cnt) {
        int2 e0 = g_edge[st + j];
        float m0 = __int_as_float(e0.y);
        float4 v0 = *(const float4*)(g_h1 + (size_t)e0.x * HD + c * 4);
        acc.x += v0.x * m0; acc.y += v0.y * m0;
        acc.z += v0.z * m0; acc.w += v0.w * m0;
    }

    float v0 = fmaxf(acc.x * dv + sb1[c * 4 + 0], 0.f);
    float v1 = fmaxf(acc.y * dv + sb1[c * 4 + 1], 0.f);
    float v2 = fmaxf(acc.z * dv + sb1[c * 4 + 2], 0.f);
    float v3 = fmaxf(acc.w * dv + sb1[c * 4 + 3], 0.f);

    float p[8];
#pragma unroll
    for (int cc = 0; cc < 8; cc++) {
        p[cc] = v0 * sW2[(c * 4 + 0) * 8 + cc]
              + v1 * sW2[(c * 4 + 1) * 8 + cc]
              + v2 * sW2[(c * 4 + 2) * 8 + cc]
              + v3 * sW2[(c * 4 + 3) * 8 + cc];
    }
#pragma unroll
    for (int cc = 0; cc < 8; cc++) {
        p[cc] += __shfl_xor_sync(0xFFFFFFFFu, p[cc], 1);
        p[cc] += __shfl_xor_sync(0xFFFFFFFFu, p[cc], 2);
    }
    if (valid) {
        if (c == 0)
            *(float4*)(g_h2 + (size_t)node * 8)     = make_float4(p[0], p[1], p[2], p[3]);
        else if (c == 1)
            *(float4*)(g_h2 + (size_t)node * 8 + 4) = make_float4(p[4], p[5], p[6], 0.f);
    }
}

// ---------------- agg layer 2 + fused bias + log_softmax ----------------
// 2 lanes per node; lane c owns feats [4c,4c+4) of 8-wide rows (col7 == 0).
__global__ __launch_bounds__(256) void k_agg2(const float* __restrict__ b2,
                                              float* __restrict__ out, int n) {
    __shared__ float sb2[8];
    int t = threadIdx.x;
    if (t < 8) sb2[t] = (t < CD) ? b2[t] : -1e30f;   // pad lane -> exp()==0
    __syncthreads();

    int node = blockIdx.x * 128 + (t >> 1);
    int c = t & 1;
    bool valid = node < n;
    if (!valid) node = n - 1;

    float dv = g_dinv[node];
    float4 h = *(const float4*)(g_h2 + (size_t)node * 8 + c * 4);
    float4 acc = make_float4(h.x * dv, h.y * dv, h.z * dv, h.w * dv);

    int st = g_rows[node], cnt = g_cnt[node];
    int j = 0;
    for (; j + 1 < cnt; j += 2) {
        int2 e0 = g_edge[st + j], e1 = g_edge[st + j + 1];
        float m0 = __int_as_float(e0.y), m1 = __int_as_float(e1.y);
        float4 v0 = *(const float4*)(g_h2 + (size_t)e0.x * 8 + c * 4);
        float4 v1 = *(const float4*)(g_h2 + (size_t)e1.x * 8 + c * 4);
        acc.x += v0.x * m0 + v1.x * m1;
        acc.y += v0.y * m0 + v1.y * m1;
        acc.z += v0.z * m0 + v1.z * m1;
        acc.w += v0.w * m0 + v1.w * m1;
    }
    if (j < cnt) {
        int2 e0 = g_edge[st + j];
        float m0 = __int_as_float(e0.y);
        float4 v0 = *(const float4*)(g_h2 + (size_t)e0.x * 8 + c * 4);
        acc.x += v0.x * m0; acc.y += v0.y * m0;
        acc.z += v0.z * m0; acc.w += v0.w * m0;
    }

    float o0 = acc.x * dv + sb2[c * 4 + 0];
    float o1 = acc.y * dv + sb2[c * 4 + 1];
    float o2 = acc.z * dv + sb2[c * 4 + 2];
    float o3 = acc.w * dv + sb2[c * 4 + 3];

    float m = fmaxf(fmaxf(o0, o1), fmaxf(o2, o3));
    m = fmaxf(m, __shfl_xor_sync(0xFFFFFFFFu, m, 1));
    float s = expf(o0 - m) + expf(o1 - m) + expf(o2 - m) + expf(o3 - m);
    s += __shfl_xor_sync(0xFFFFFFFFu, s, 1);
    float l = m + logf(s);

    if (valid) {
        float* op = out + (size_t)node * CD + c * 4;
        op[0] = o0 - l; op[1] = o1 - l; op[2] = o2 - l;
        if (c == 0) op[3] = o3 - l;
    }
}

// ---------------- launch ----------------

extern "C" void kernel_launch(void* const* d_in, const int* in_sizes, int n_in,
                              void* d_out, int out_size) {
    const float* x  = (const float*)d_in[0];
    const int*   ei = (const int*)  d_in[1];
    const float* W1 = (const float*)d_in[2];
    const float* b1 = (const float*)d_in[3];
    const float* W2 = (const float*)d_in[4];
    const float* b2 = (const float*)d_in[5];

    const int n = in_sizes[0] / FIN;
    const int e = in_sizes[1] / 2;
    const int* src = ei;
    const int* dst = ei + e;

    const int NB = (n + 255) / 256;        // gemm node-blocks (391)
    const int GA = NB / 4;                 // gemm part A (overlaps edge count)
    const int GB = NB - GA;                // gemm part B (overlaps CSR fill)
    const int nbScan = (n + 1023) / 1024;  // <= 128

    k_zero<<<(n + 255) / 256, 256>>>(n);
    kA<<<GA + 1024, 256>>>(dst, e, x, W1, n, GA);
    k_scan1_rsqrt<<<nbScan + (n + 255) / 256, 256>>>(n, nbScan);
    k_scan2<<<1, 128>>>(nbScan);
    k_scan3<<<(n + 255) / 256, 256>>>(n);
    kB<<<GB + 2048, 256>>>(src, dst, e, x, W1, n, GB, GA);
    k_agg1<<<(n + 63) / 64, 256>>>(b1, W2, n);
    k_agg2<<<(n + 127) / 128, 256>>>(b2, (float*)d_out, n);
}